// round 1
// baseline (speedup 1.0000x reference)
#include <cuda_runtime.h>
#include <cstdint>

// MyLoc1d: out[b,o,p] = scale * sum_{c,f} x[b,c,p+f] * filt[o,c,p,f]
// x:    (32, 128, 1024) f32
// filt: (128, 128, 1017, 8) f32
// out:  (32, 128, 1017) f32, scale = 1/sqrt(128*8) = 1/32
//
// One block per p (1017 blocks), 128 threads, thread == o.
// All 32 batches packed into 16 f32x2 accumulators per thread.
// Filter: per-thread contiguous 32B loads (2x LDG.128), streamed once.
// x: staged to smem [c][col][b], col stride padded to 36 floats
//    (conflict-free stores, aligned 128-bit broadcast reads).

#define C_DIM 128
#define P_DIM 1017
#define F_DIM 8
#define D_DIM 1024
#define O_DIM 128

typedef unsigned long long ull;

__device__ __forceinline__ void ffma2(ull& d, ull a, ull b) {
    asm("fma.rn.f32x2 %0, %1, %2, %0;" : "+l"(d) : "l"(a), "l"(b));
}

__device__ __forceinline__ ull pk2(float a, float b) {
    ull r;
    asm("mov.b64 %0, {%1, %2};" : "=l"(r) : "f"(a), "f"(b));
    return r;
}

__device__ __forceinline__ void upk2(ull v, float& a, float& b) {
    asm("mov.b64 {%0, %1}, %2;" : "=f"(a), "=f"(b) : "l"(v));
}

// smem layout: xs[c_local][col][b] with col stride 36 floats (pad 32->36):
//   addr = c_local*288 + col*36 + b
// stores: lanes vary (col, b) -> bank = (4*col + b) % 32, all distinct -> conflict-free
// reads: warp-uniform address -> broadcast, 16B-aligned (36*4=144, 288*4=1152 both %16==0)

__global__ void __launch_bounds__(128, 6)
loc1d_kernel(const float* __restrict__ x,
             const float* __restrict__ filt,
             float* __restrict__ out)
{
    __shared__ __align__(16) float xs[8 * 288];

    const int t = threadIdx.x;      // 0..127
    const int p = blockIdx.x;       // 0..1016
    const int o = t;                // thread == output channel

    ull acc[16];
#pragma unroll
    for (int k = 0; k < 16; ++k) acc[k] = 0ull;

    // x-stage mapping: lin = t + r*128, r = 0..15
    //   col     = lin & 7        (fixed per thread = t & 7)
    //   b       = (lin>>3)&31    = ((t>>3)&15) + 16*(r&1)
    //   c_local = lin >> 8       = r >> 1
    const int colc = t & 7;
    const int b0   = (t >> 3) & 15;

    for (int ct = 0; ct < 16; ++ct) {
        const int cbase = ct * 8;

        __syncthreads();  // previous tile's reads complete before overwrite
#pragma unroll
        for (int r = 0; r < 16; ++r) {
            const int b  = b0 + ((r & 1) << 4);
            const int cl = r >> 1;
            const int c  = cbase + cl;
            // p + colc <= 1016 + 7 = 1023 < 1024: always in bounds
            xs[cl * 288 + colc * 36 + b] =
                __ldg(&x[((size_t)(b * C_DIM + c) << 10) + p + colc]);
        }
        __syncthreads();

#pragma unroll
        for (int cl = 0; cl < 8; ++cl) {
            const int c = cbase + cl;
            // filt[o][c][p][0..7] : 32 contiguous, 32B-aligned bytes
            const float4* wp = reinterpret_cast<const float4*>(
                filt + ((size_t)(o * C_DIM + c) * P_DIM + p) * F_DIM);
            const float4 w0 = __ldg(&wp[0]);
            const float4 w1 = __ldg(&wp[1]);
            const float wv[8] = {w0.x, w0.y, w0.z, w0.w,
                                 w1.x, w1.y, w1.z, w1.w};
#pragma unroll
            for (int f = 0; f < 8; ++f) {
                const ull wb = pk2(wv[f], wv[f]);
                const ulonglong2* xr = reinterpret_cast<const ulonglong2*>(
                    &xs[cl * 288 + f * 36]);
#pragma unroll
                for (int j = 0; j < 8; ++j) {
                    const ulonglong2 v = xr[j];   // batches 4j..4j+3 (LDS.128 bcast)
                    ffma2(acc[2 * j],     wb, v.x);
                    ffma2(acc[2 * j + 1], wb, v.y);
                }
            }
        }
    }

    // acc[k] holds batches (2k, 2k+1). out[b][o][p] = (b*128 + o)*1017 + p
    const float scale = 0.03125f;  // 1/32
#pragma unroll
    for (int k = 0; k < 16; ++k) {
        float a0, a1;
        upk2(acc[k], a0, a1);
        const int b = 2 * k;
        out[((size_t)(b * O_DIM) + o) * P_DIM + p]       = a0 * scale;
        out[((size_t)((b + 1) * O_DIM) + o) * P_DIM + p] = a1 * scale;
    }
}

extern "C" void kernel_launch(void* const* d_in, const int* in_sizes, int n_in,
                              void* d_out, int out_size)
{
    const float* x    = (const float*)d_in[0];
    const float* filt = (const float*)d_in[1];
    float* out        = (float*)d_out;

    dim3 grid(P_DIM);
    dim3 block(128);
    loc1d_kernel<<<grid, block>>>(x, filt, out);
}

// round 2
// speedup vs baseline: 1.1017x; 1.1017x over previous
#include <cuda_runtime.h>
#include <cstdint>

// MyLoc1d: out[b,o,p] = (1/32) * sum_{c,f} x[b,c,p+f] * filt[o,c,p,f]
// x: (32,128,1024) f32; filt: (128,128,1017,8) f32; out: (32,128,1017) f32
//
// Block: 256 threads = 128 o x 2 batch-halves. P_TILE=3 (1017 = 3*339).
// Per c: stage W (128o x 3p x 8f = 3072 floats) coalesced into smem,
//        stage x (10 cols x 32 b) into smem; double-buffered, 1 sync/iter.
// Compute: thread owns (o, 16 batches, 3 p). x read as broadcast LDS.128
// with sliding 3-col register window; W read conflict-free (stride 28).

#define C_DIM 128
#define P_DIM 1017
#define O_DIM 128
#define PT 3              // patches per block/thread
#define NBLK 339          // 1017 / 3

typedef unsigned long long ull;

__device__ __forceinline__ void ffma2(ull& d, ull a, ull b) {
    asm("fma.rn.f32x2 %0, %1, %2, %0;" : "+l"(d) : "l"(a), "l"(b));
}
__device__ __forceinline__ ull pk2(float a) {
    ull r;
    asm("mov.b64 %0, {%1, %1};" : "=l"(r) : "f"(a));
    return r;
}
__device__ __forceinline__ void upk2(ull v, float& a, float& b) {
    asm("mov.b64 {%0, %1}, %2;" : "=f"(a), "=f"(b) : "l"(v));
}

#define W_STRIDE 28            // per-o smem stride (24 floats + pad, conflict-free quads)
#define X_STRIDE 36            // per-col smem stride (32 b + pad)
#define W_SMEM   (O_DIM * W_STRIDE)   // 3584 floats
#define X_COLS   (PT + 7)             // 10
#define X_SMEM   (X_COLS * X_STRIDE)  // 360 floats

struct Stage {
    float4 w[3];
    float  xv[2];
};

__device__ __forceinline__ void ldg_stage(Stage& s,
                                          const float* __restrict__ x,
                                          const float* __restrict__ filt,
                                          int c, int p0, int t)
{
#pragma unroll
    for (int k = 0; k < 3; ++k) {
        int g4 = t + 256 * k;          // 0..767 float4s of the W slab
        int oo = g4 / 6;
        int j4 = g4 % 6;
        const float4* src = reinterpret_cast<const float4*>(
            filt + (((size_t)(oo * C_DIM + c)) * P_DIM + p0) * 8);
        s.w[k] = __ldg(src + j4);
    }
#pragma unroll
    for (int k = 0; k < 2; ++k) {
        int idx = t + 256 * k;         // 0..319 floats of the x slab
        if (idx < X_COLS * 32) {
            int b   = idx / X_COLS;
            int col = idx % X_COLS;
            s.xv[k] = __ldg(x + (((size_t)(b * C_DIM + c)) << 10) + p0 + col);
        }
    }
}

__device__ __forceinline__ void sts_stage(const Stage& s, float* ws, float* xs, int t)
{
#pragma unroll
    for (int k = 0; k < 3; ++k) {
        int g4 = t + 256 * k;
        int oo = g4 / 6;
        int j4 = g4 % 6;
        *reinterpret_cast<float4*>(&ws[oo * W_STRIDE + j4 * 4]) = s.w[k];
    }
#pragma unroll
    for (int k = 0; k < 2; ++k) {
        int idx = t + 256 * k;
        if (idx < X_COLS * 32) {
            int b   = idx / X_COLS;
            int col = idx % X_COLS;
            xs[col * X_STRIDE + b] = s.xv[k];
        }
    }
}

__global__ void __launch_bounds__(256, 2)
loc1d_kernel(const float* __restrict__ x,
             const float* __restrict__ filt,
             float* __restrict__ out)
{
    __shared__ __align__(16) float ws[2][W_SMEM];
    __shared__ __align__(16) float xs[2][X_SMEM];

    const int t  = threadIdx.x;
    const int o  = t & 127;
    const int bh = t >> 7;                 // batch half: batches bh*16 .. bh*16+15
    const int p0 = blockIdx.x * PT;

    ull acc[PT][8];                        // [p][2q+h]: batches bh*16+4q+2h..+1
#pragma unroll
    for (int p = 0; p < PT; ++p)
#pragma unroll
        for (int k = 0; k < 8; ++k) acc[p][k] = 0ull;

    Stage st;
    ldg_stage(st, x, filt, 0, p0, t);

    for (int c = 0; c < C_DIM; ++c) {
        const int s = c & 1;
        sts_stage(st, ws[s], xs[s], t);
        __syncthreads();
        if (c + 1 < C_DIM) ldg_stage(st, x, filt, c + 1, p0, t);

        // W for this thread's o: 24 floats = w[p][f]
        float w[PT][8];
        const float4* wr = reinterpret_cast<const float4*>(&ws[s][o * W_STRIDE]);
#pragma unroll
        for (int j = 0; j < 6; ++j)
            reinterpret_cast<float4*>(&w[0][0])[j] = wr[j];

#pragma unroll
        for (int q = 0; q < 4; ++q) {
            const float* xb = &xs[s][bh * 16 + q * 4];
            // sliding 3-col window over f
            ulonglong2 x0 = *reinterpret_cast<const ulonglong2*>(xb + 0 * X_STRIDE);
            ulonglong2 x1 = *reinterpret_cast<const ulonglong2*>(xb + 1 * X_STRIDE);
            ulonglong2 x2;
#pragma unroll
            for (int f = 0; f < 8; ++f) {
                x2 = *reinterpret_cast<const ulonglong2*>(xb + (f + 2) * X_STRIDE);
                {
                    ull wb = pk2(w[0][f]);
                    ffma2(acc[0][2 * q],     wb, x0.x);
                    ffma2(acc[0][2 * q + 1], wb, x0.y);
                }
                {
                    ull wb = pk2(w[1][f]);
                    ffma2(acc[1][2 * q],     wb, x1.x);
                    ffma2(acc[1][2 * q + 1], wb, x1.y);
                }
                {
                    ull wb = pk2(w[2][f]);
                    ffma2(acc[2][2 * q],     wb, x2.x);
                    ffma2(acc[2][2 * q + 1], wb, x2.y);
                }
                x0 = x1;
                x1 = x2;
            }
        }
        __syncthreads();
    }

    // out[b][o][p] = (b*128 + o)*1017 + p
    const float scale = 0.03125f;
#pragma unroll
    for (int p = 0; p < PT; ++p) {
#pragma unroll
        for (int q = 0; q < 4; ++q) {
#pragma unroll
            for (int h = 0; h < 2; ++h) {
                float a0, a1;
                upk2(acc[p][2 * q + h], a0, a1);
                int b = bh * 16 + 4 * q + 2 * h;
                out[((size_t)(b * O_DIM) + o) * P_DIM + p0 + p]       = a0 * scale;
                out[((size_t)((b + 1) * O_DIM) + o) * P_DIM + p0 + p] = a1 * scale;
            }
        }
    }
}

extern "C" void kernel_launch(void* const* d_in, const int* in_sizes, int n_in,
                              void* d_out, int out_size)
{
    const float* x    = (const float*)d_in[0];
    const float* filt = (const float*)d_in[1];
    float* out        = (float*)d_out;

    loc1d_kernel<<<NBLK, 256>>>(x, filt, out);
}